// round 7
// baseline (speedup 1.0000x reference)
#include <cuda_runtime.h>
#include <cstdint>

#define B_DIM 1024
#define T_DIM 200
#define E_DIM 128
#define H_DIM 64
#define T2    128   // t-half tile per CTA (2 CTAs per batch row)

// smem layout (floats):
//   ks   [E_DIM][T2]     = 16384
//   weff [E_DIM][H_DIM]  =  8192
//   qs   [E_DIM]         =   128
//   cs   [H_DIM]         =    64
//   w1s  [H_DIM]         =    64
#define SMEM_FLOATS (E_DIM * T2 + E_DIM * H_DIM + E_DIM + H_DIM + H_DIM)
#define SMEM_BYTES  (SMEM_FLOATS * 4)

// packed f32x2 FMA: acc = a*b + acc (elementwise on both halves)
#define FMA2(accv, av, bv) \
    asm("fma.rn.f32x2 %0, %1, %2, %0;" : "+l"(accv) : "l"(av), "l"(bv))

__global__ void __launch_bounds__(256, 2)
lau_kernel(const float* __restrict__ query,   // [B,1,E]
           const float* __restrict__ keys,    // [B,T,E]
           const float* __restrict__ W0,      // [4E,H]
           const float* __restrict__ b0,      // [H]
           const float* __restrict__ W1,      // [H,1]
           const float* __restrict__ b1,      // [1]
           float* __restrict__ out)           // [B,T,1]
{
    extern __shared__ float smem[];
    float* ks   = smem;                        // [E][T2]
    float* weff = smem + E_DIM * T2;           // [E][H]
    float* qs   = weff + E_DIM * H_DIM;
    float* cs   = qs + E_DIM;
    float* w1s  = cs + H_DIM;

    const int b     = blockIdx.x;
    const int thalf = blockIdx.y;              // 0 or 1: t range [thalf*128, +128)
    const int tid   = threadIdx.x;

    // ---- stage q and W1 ----
    if (tid < E_DIM) qs[tid] = query[b * E_DIM + tid];
    if (tid >= E_DIM && tid < E_DIM + H_DIM) w1s[tid - E_DIM] = W1[tid - E_DIM];
    __syncthreads();

    // ---- transpose-load this CTA's keys half into ks[e][t] (zero-pad) ----
    // 2 threads per t row: thread covers 64 e values (16 float4 LDGs, high MLP)
    {
        const int t_loc  = tid >> 1;               // 0..127
        const int e_base = (tid & 1) * 64;         // 0 or 64
        const int t_glob = thalf * T2 + t_loc;
        const bool valid = t_glob < T_DIM;
        const float4* krow = (const float4*)(keys +
            ((long)b * T_DIM + (valid ? t_glob : 0)) * E_DIM + e_base);
        #pragma unroll
        for (int i = 0; i < 16; i++) {
            float4 v = valid ? krow[i] : make_float4(0.f, 0.f, 0.f, 0.f);
            int e = e_base + 4 * i;
            ks[(e + 0) * T2 + t_loc] = v.x;
            ks[(e + 1) * T2 + t_loc] = v.y;
            ks[(e + 2) * T2 + t_loc] = v.z;
            ks[(e + 3) * T2 + t_loc] = v.w;
        }
    }

    // ---- build Weff[e][h] = W0k - W0d + q[e]*W0m  (vectorized float4) ----
    {
        const float4* W0k = (const float4*)(W0 + 128 * H_DIM);
        const float4* W0d = (const float4*)(W0 + 256 * H_DIM);
        const float4* W0m = (const float4*)(W0 + 384 * H_DIM);
        float4* wf = (float4*)weff;
        const int NV = E_DIM * H_DIM / 4;  // 2048, 8 iters per thread
        #pragma unroll 2
        for (int i = tid; i < NV; i += 256) {
            int e = i >> 4;                // H/4 = 16 float4 per e-row
            float q = qs[e];
            float4 a = W0k[i], d = W0d[i], m = W0m[i];
            float4 r;
            r.x = a.x - d.x + q * m.x;
            r.y = a.y - d.y + q * m.y;
            r.z = a.z - d.z + q * m.z;
            r.w = a.w - d.w + q * m.w;
            wf[i] = r;
        }
    }

    // ---- c[h] = b0[h] + sum_e q[e]*(W0q[e][h] + W0d[e][h]) ----
    if (tid < H_DIM) {
        float acc = b0[tid];
        #pragma unroll 8
        for (int e = 0; e < E_DIM; e++) {
            acc += qs[e] * (W0[e * H_DIM + tid] + W0[(256 + e) * H_DIM + tid]);
        }
        cs[tid] = acc;
    }
    __syncthreads();

    // ---- main GEMM: h_pre[t][h] = c[h] + sum_e ks[e][t]*Weff[e][h] ----
    // 256 threads: 32 t-groups x 8 h-groups; thread tile 4t x 8h
    const int tc = tid & 7;    // h-group 0..7
    const int tr = tid >> 3;   // t-group 0..31
    const int h0 = tc * 8;
    const int t0 = tr * 4;

    // acc[i][j]: row t0+i, packed h pair (h0+2j, h0+2j+1); init with c
    unsigned long long acc[4][4];
    {
        const unsigned long long* cp = (const unsigned long long*)(cs + h0);
        unsigned long long c0 = cp[0], c1 = cp[1], c2 = cp[2], c3 = cp[3];
        #pragma unroll
        for (int i = 0; i < 4; i++) {
            acc[i][0] = c0; acc[i][1] = c1; acc[i][2] = c2; acc[i][3] = c3;
        }
    }

    #pragma unroll 4
    for (int e = 0; e < E_DIM; e++) {
        // b-operand: Weff[e][h0..h0+7] as 4 packed f32x2 (2x LDS.128)
        const ulonglong2* bp = (const ulonglong2*)(weff + e * H_DIM + h0);
        ulonglong2 bA = bp[0], bB = bp[1];
        // a-operand: ks[e][t0..t0+3] (1x LDS.128, broadcast within 8-lane group)
        const float4* ap = (const float4*)(ks + e * T2 + t0);
        float4 a0 = ap[0];
        float av[4] = {a0.x, a0.y, a0.z, a0.w};
        #pragma unroll
        for (int i = 0; i < 4; i++) {
            unsigned long long apk;
            asm("mov.b64 %0, {%1, %1};" : "=l"(apk) : "f"(av[i]));
            FMA2(acc[i][0], apk, bA.x);
            FMA2(acc[i][1], apk, bA.y);
            FMA2(acc[i][2], apk, bB.x);
            FMA2(acc[i][3], apk, bB.y);
        }
    }

    // ---- epilogue: relu, dot with W1, reduce over 8 h-groups, store ----
    float w1r[8];
    #pragma unroll
    for (int j = 0; j < 8; j++) w1r[j] = w1s[h0 + j];
    const float bias1 = b1[0];

    #pragma unroll
    for (int i = 0; i < 4; i++) {
        float s = 0.f;
        #pragma unroll
        for (int j = 0; j < 4; j++) {
            float lo, hi;
            asm("mov.b64 {%0, %1}, %2;" : "=f"(lo), "=f"(hi) : "l"(acc[i][j]));
            s += fmaxf(lo, 0.f) * w1r[2 * j] + fmaxf(hi, 0.f) * w1r[2 * j + 1];
        }
        // reduce across the 8 h-threadcols (contiguous 8-lane groups in warp)
        s += __shfl_xor_sync(0xffffffffu, s, 1);
        s += __shfl_xor_sync(0xffffffffu, s, 2);
        s += __shfl_xor_sync(0xffffffffu, s, 4);
        const int t = thalf * T2 + t0 + i;
        if (tc == 0 && t < T_DIM) out[b * T_DIM + t] = s + bias1;
    }
}

extern "C" void kernel_launch(void* const* d_in, const int* in_sizes, int n_in,
                              void* d_out, int out_size)
{
    const float* query = (const float*)d_in[0];
    const float* keys  = (const float*)d_in[1];
    const float* W0    = (const float*)d_in[2];
    const float* b0    = (const float*)d_in[3];
    const float* W1    = (const float*)d_in[4];
    const float* b1    = (const float*)d_in[5];
    float* out = (float*)d_out;

    cudaFuncSetAttribute(lau_kernel, cudaFuncAttributeMaxDynamicSharedMemorySize, SMEM_BYTES);
    dim3 grid(B_DIM, 2);
    lau_kernel<<<grid, 256, SMEM_BYTES>>>(query, keys, W0, b0, W1, b1, out);
}

// round 9
// speedup vs baseline: 1.3797x; 1.3797x over previous
#include <cuda_runtime.h>
#include <cstdint>

#define B_DIM 1024
#define T_DIM 200
#define E_DIM 128
#define H_DIM 64
#define T2    128   // t-half tile per CTA (2 CTAs per batch row)
#define NTHREADS 128

// smem layout (floats):
//   ks   [E_DIM][T2]     = 16384
//   weff [E_DIM][H_DIM]  =  8192
//   qs   [E_DIM]         =   128
//   cs   [H_DIM]         =    64
//   w1s  [H_DIM]         =    64
#define SMEM_FLOATS (E_DIM * T2 + E_DIM * H_DIM + E_DIM + H_DIM + H_DIM)
#define SMEM_BYTES  (SMEM_FLOATS * 4)

// packed f32x2 FMA: acc = a*b + acc (elementwise on both halves)
#define FMA2(accv, av, bv) \
    asm("fma.rn.f32x2 %0, %1, %2, %0;" : "+l"(accv) : "l"(av), "l"(bv))

__global__ void __launch_bounds__(NTHREADS, 2)
lau_kernel(const float* __restrict__ query,   // [B,1,E]
           const float* __restrict__ keys,    // [B,T,E]
           const float* __restrict__ W0,      // [4E,H]
           const float* __restrict__ b0,      // [H]
           const float* __restrict__ W1,      // [H,1]
           const float* __restrict__ b1,      // [1]
           float* __restrict__ out)           // [B,T,1]
{
    extern __shared__ float smem[];
    float* ks   = smem;                        // [E][T2]
    float* weff = smem + E_DIM * T2;           // [E][H]
    float* qs   = weff + E_DIM * H_DIM;
    float* cs   = qs + E_DIM;
    float* w1s  = cs + H_DIM;

    const int b     = blockIdx.x;
    const int thalf = blockIdx.y;              // 0 or 1: t range [thalf*128, +128)
    const int tid   = threadIdx.x;

    // ---- stage q and W1 ----
    qs[tid] = query[b * E_DIM + tid];          // NTHREADS == E_DIM
    if (tid < H_DIM) w1s[tid] = W1[tid];
    __syncthreads();

    // ---- transpose-load this CTA's keys half into ks[e][t] (zero-pad) ----
    // 1 thread per t row: 32 float4 LDGs (very high MLP), STS warp-contiguous in t
    {
        const int t_loc  = tid;                    // 0..127
        const int t_glob = thalf * T2 + t_loc;
        const bool valid = t_glob < T_DIM;
        const float4* krow = (const float4*)(keys +
            ((long)b * T_DIM + (valid ? t_glob : 0)) * E_DIM);
        #pragma unroll
        for (int i = 0; i < 32; i++) {
            float4 v = valid ? krow[i] : make_float4(0.f, 0.f, 0.f, 0.f);
            int e = 4 * i;
            ks[(e + 0) * T2 + t_loc] = v.x;
            ks[(e + 1) * T2 + t_loc] = v.y;
            ks[(e + 2) * T2 + t_loc] = v.z;
            ks[(e + 3) * T2 + t_loc] = v.w;
        }
    }

    // ---- build Weff[e][h] = W0k - W0d + q[e]*W0m  (vectorized float4) ----
    {
        const float4* W0k = (const float4*)(W0 + 128 * H_DIM);
        const float4* W0d = (const float4*)(W0 + 256 * H_DIM);
        const float4* W0m = (const float4*)(W0 + 384 * H_DIM);
        float4* wf = (float4*)weff;
        const int NV = E_DIM * H_DIM / 4;  // 2048, 16 iters per thread
        #pragma unroll 4
        for (int i = tid; i < NV; i += NTHREADS) {
            int e = i >> 4;                // H/4 = 16 float4 per e-row
            float q = qs[e];
            float4 a = W0k[i], d = W0d[i], m = W0m[i];
            float4 r;
            r.x = a.x - d.x + q * m.x;
            r.y = a.y - d.y + q * m.y;
            r.z = a.z - d.z + q * m.z;
            r.w = a.w - d.w + q * m.w;
            wf[i] = r;
        }
    }

    // ---- c[h] = b0[h] + sum_e q[e]*(W0q[e][h] + W0d[e][h]) ----
    if (tid < H_DIM) {
        float acc = b0[tid];
        #pragma unroll 8
        for (int e = 0; e < E_DIM; e++) {
            acc += qs[e] * (W0[e * H_DIM + tid] + W0[(256 + e) * H_DIM + tid]);
        }
        cs[tid] = acc;
    }
    __syncthreads();

    // ---- main GEMM: h_pre[t][h] = c[h] + sum_e ks[e][t]*Weff[e][h] ----
    // 128 threads: 16 t-groups x 8 h-groups; thread tile 8t x 8h
    const int tc = tid & 7;    // h-group 0..7
    const int tr = tid >> 3;   // t-group 0..15
    const int h0 = tc * 8;
    const int t0 = tr * 8;

    // acc[i][j]: row t0+i, packed h pair (h0+2j, h0+2j+1); init with c
    unsigned long long acc[8][4];
    {
        const unsigned long long* cp = (const unsigned long long*)(cs + h0);
        unsigned long long c0 = cp[0], c1 = cp[1], c2 = cp[2], c3 = cp[3];
        #pragma unroll
        for (int i = 0; i < 8; i++) {
            acc[i][0] = c0; acc[i][1] = c1; acc[i][2] = c2; acc[i][3] = c3;
        }
    }

    #pragma unroll 4
    for (int e = 0; e < E_DIM; e++) {
        // b-operand: Weff[e][h0..h0+7] as 4 packed f32x2 (2x LDS.128)
        const ulonglong2* bp = (const ulonglong2*)(weff + e * H_DIM + h0);
        ulonglong2 bA = bp[0], bB = bp[1];
        // a-operand: ks[e][t0..t0+7] (2x LDS.128)
        const float4* ap = (const float4*)(ks + e * T2 + t0);
        float4 a0 = ap[0], a1 = ap[1];
        float av[8] = {a0.x, a0.y, a0.z, a0.w, a1.x, a1.y, a1.z, a1.w};
        #pragma unroll
        for (int i = 0; i < 8; i++) {
            unsigned long long apk;
            asm("mov.b64 %0, {%1, %1};" : "=l"(apk) : "f"(av[i]));
            FMA2(acc[i][0], apk, bA.x);
            FMA2(acc[i][1], apk, bA.y);
            FMA2(acc[i][2], apk, bB.x);
            FMA2(acc[i][3], apk, bB.y);
        }
    }

    // ---- epilogue: relu, dot with W1, reduce over 8 h-groups, store ----
    float w1r[8];
    #pragma unroll
    for (int j = 0; j < 8; j++) w1r[j] = w1s[h0 + j];
    const float bias1 = b1[0];

    #pragma unroll
    for (int i = 0; i < 8; i++) {
        float s = 0.f;
        #pragma unroll
        for (int j = 0; j < 4; j++) {
            float lo, hi;
            asm("mov.b64 {%0, %1}, %2;" : "=f"(lo), "=f"(hi) : "l"(acc[i][j]));
            s += fmaxf(lo, 0.f) * w1r[2 * j] + fmaxf(hi, 0.f) * w1r[2 * j + 1];
        }
        // reduce across the 8 h-threadcols (contiguous 8-lane groups in warp)
        s += __shfl_xor_sync(0xffffffffu, s, 1);
        s += __shfl_xor_sync(0xffffffffu, s, 2);
        s += __shfl_xor_sync(0xffffffffu, s, 4);
        const int t = thalf * T2 + t0 + i;
        if (tc == 0 && t < T_DIM) out[b * T_DIM + t] = s + bias1;
    }
}

extern "C" void kernel_launch(void* const* d_in, const int* in_sizes, int n_in,
                              void* d_out, int out_size)
{
    const float* query = (const float*)d_in[0];
    const float* keys  = (const float*)d_in[1];
    const float* W0    = (const float*)d_in[2];
    const float* b0    = (const float*)d_in[3];
    const float* W1    = (const float*)d_in[4];
    const float* b1    = (const float*)d_in[5];
    float* out = (float*)d_out;

    cudaFuncSetAttribute(lau_kernel, cudaFuncAttributeMaxDynamicSharedMemorySize, SMEM_BYTES);
    dim3 grid(B_DIM, 2);
    lau_kernel<<<grid, NTHREADS, SMEM_BYTES>>>(query, keys, W0, b0, W1, b1, out);
}

// round 14
// speedup vs baseline: 1.5095x; 1.0941x over previous
#include <cuda_runtime.h>
#include <cstdint>

#define B_DIM 1024
#define T_DIM 200
#define E_DIM 128
#define H_DIM 64
#define T2    128   // t-half tile per CTA (2 CTAs per batch row)
#define NTH   128

// smem layout (floats):
//   ks   [E_DIM][T2]     = 16384
//   weff [E_DIM][H_DIM]  =  8192
//   qs   [E_DIM]         =   128
//   cs   [H_DIM]         =    64
//   w1s  [H_DIM]         =    64
//   csp  [8][H_DIM]      =   512   (cs partials)
#define SMEM_FLOATS (E_DIM * T2 + E_DIM * H_DIM + E_DIM + H_DIM + H_DIM + 8 * H_DIM)
#define SMEM_BYTES  (SMEM_FLOATS * 4)

// packed f32x2 FMA: acc = a*b + acc (elementwise on both halves)
#define FMA2(accv, av, bv) \
    asm("fma.rn.f32x2 %0, %1, %2, %0;" : "+l"(accv) : "l"(av), "l"(bv))

__global__ void __launch_bounds__(NTH, 2)
lau_kernel(const float* __restrict__ query,   // [B,1,E]
           const float* __restrict__ keys,    // [B,T,E]
           const float* __restrict__ W0,      // [4E,H]
           const float* __restrict__ b0,      // [H]
           const float* __restrict__ W1,      // [H,1]
           const float* __restrict__ b1,      // [1]
           float* __restrict__ out)           // [B,T,1]
{
    extern __shared__ float smem[];
    float* ks   = smem;                        // [E][T2]
    float* weff = smem + E_DIM * T2;           // [E][H]
    float* qs   = weff + E_DIM * H_DIM;
    float* cs   = qs + E_DIM;
    float* w1s  = cs + H_DIM;
    float* csp  = w1s + H_DIM;                 // [8][H]

    const int b     = blockIdx.x;
    const int thalf = blockIdx.y;              // 0 or 1: t range [thalf*128, +128)
    const int tid   = threadIdx.x;

    // ---- stage q and W1 ----
    qs[tid] = query[b * E_DIM + tid];          // NTH == E_DIM
    if (tid < H_DIM) w1s[tid] = W1[tid];
    __syncthreads();

    // ---- transpose-load this CTA's keys half into ks[e][t] (zero-pad) ----
    // 1 thread per t row: 32 float4 LDGs (high MLP), STS warp-contiguous in t
    {
        const int t_loc  = tid;                    // 0..127
        const int t_glob = thalf * T2 + t_loc;
        const bool valid = t_glob < T_DIM;
        const float4* krow = (const float4*)(keys +
            ((long)b * T_DIM + (valid ? t_glob : 0)) * E_DIM);
        #pragma unroll
        for (int i = 0; i < 32; i++) {
            float4 v = valid ? krow[i] : make_float4(0.f, 0.f, 0.f, 0.f);
            int e = 4 * i;
            ks[(e + 0) * T2 + t_loc] = v.x;
            ks[(e + 1) * T2 + t_loc] = v.y;
            ks[(e + 2) * T2 + t_loc] = v.z;
            ks[(e + 3) * T2 + t_loc] = v.w;
        }
    }

    // ---- build Weff[e][h] = W0k - W0d + q[e]*W0m  (vectorized float4) ----
    {
        const float4* W0k = (const float4*)(W0 + 128 * H_DIM);
        const float4* W0d = (const float4*)(W0 + 256 * H_DIM);
        const float4* W0m = (const float4*)(W0 + 384 * H_DIM);
        float4* wf = (float4*)weff;
        const int NV = E_DIM * H_DIM / 4;  // 2048, 16 iters per thread
        #pragma unroll 4
        for (int i = tid; i < NV; i += NTH) {
            int e = i >> 4;                // H/4 = 16 float4 per e-row
            float q = qs[e];
            float4 a = W0k[i], d = W0d[i], m = W0m[i];
            float4 r;
            r.x = a.x - d.x + q * m.x;
            r.y = a.y - d.y + q * m.y;
            r.z = a.z - d.z + q * m.z;
            r.w = a.w - d.w + q * m.w;
            wf[i] = r;
        }
    }

    // ---- cs partials: all 128 threads, float4-coalesced ----
    // part = tid>>4 (0..7) covers e in [part*16, +16); h4 = tid&15 covers 4 h
    {
        const int part  = tid >> 4;
        const int h4    = tid & 15;
        const int e0    = part * 16;
        const float4* W0q4 = (const float4*)W0;             // rows 0..127
        const float4* W0d4 = (const float4*)(W0 + 256 * H_DIM);
        float4 acc = make_float4(0.f, 0.f, 0.f, 0.f);
        #pragma unroll 4
        for (int i = 0; i < 16; i++) {
            const int e = e0 + i;
            const float q = qs[e];
            float4 a = W0q4[e * 16 + h4];
            float4 d = W0d4[e * 16 + h4];
            acc.x += q * (a.x + d.x);
            acc.y += q * (a.y + d.y);
            acc.z += q * (a.z + d.z);
            acc.w += q * (a.w + d.w);
        }
        ((float4*)csp)[part * 16 + h4] = acc;
    }
    __syncthreads();

    // ---- cs reduction (warps 0-1, 8 LDS each), runs before their GEMM ----
    if (tid < H_DIM) {
        float s = b0[tid];
        #pragma unroll
        for (int p = 0; p < 8; p++) s += csp[p * H_DIM + tid];
        cs[tid] = s;
    }

    // ---- main GEMM: pre[t][h] = sum_e ks[e][t]*Weff[e][h]  (software pipelined) ----
    // 128 threads: 16 t-groups x 8 h-groups; thread tile 8t x 8h
    const int tc = tid & 7;    // h-group 0..7
    const int tr = tid >> 3;   // t-group 0..15
    const int h0 = tc * 8;
    const int t0 = tr * 8;

    unsigned long long acc[8][4];
    #pragma unroll
    for (int i = 0; i < 8; i++)
        #pragma unroll
        for (int j = 0; j < 4; j++) acc[i][j] = 0ull;

    // double-buffered operand registers
    ulonglong2 bA[2], bB[2];
    float4 a0[2], a1[2];
    {
        const ulonglong2* bp = (const ulonglong2*)(weff + h0);
        bA[0] = bp[0]; bB[0] = bp[1];
        const float4* ap = (const float4*)(ks + t0);
        a0[0] = ap[0]; a1[0] = ap[1];
    }

    #pragma unroll 4
    for (int e = 0; e < E_DIM; e++) {
        const int cur = e & 1, nxt = cur ^ 1;
        if (e + 1 < E_DIM) {
            const ulonglong2* bp = (const ulonglong2*)(weff + (e + 1) * H_DIM + h0);
            bA[nxt] = bp[0]; bB[nxt] = bp[1];
            const float4* ap = (const float4*)(ks + (e + 1) * T2 + t0);
            a0[nxt] = ap[0]; a1[nxt] = ap[1];
        }
        float av[8] = {a0[cur].x, a0[cur].y, a0[cur].z, a0[cur].w,
                       a1[cur].x, a1[cur].y, a1[cur].z, a1[cur].w};
        #pragma unroll
        for (int i = 0; i < 8; i++) {
            unsigned long long apk;
            asm("mov.b64 %0, {%1, %1};" : "=l"(apk) : "f"(av[i]));
            FMA2(acc[i][0], apk, bA[cur].x);
            FMA2(acc[i][1], apk, bA[cur].y);
            FMA2(acc[i][2], apk, bB[cur].x);
            FMA2(acc[i][3], apk, bB[cur].y);
        }
    }

    __syncthreads();   // cs[] complete (written by warps 0-1 before their GEMM)

    // ---- epilogue: add cs, relu, dot with W1, reduce over 8 h-groups, store ----
    float w1r[8], csr[8];
    #pragma unroll
    for (int j = 0; j < 8; j++) { w1r[j] = w1s[h0 + j]; csr[j] = cs[h0 + j]; }
    const float bias1 = b1[0];

    #pragma unroll
    for (int i = 0; i < 8; i++) {
        float s = 0.f;
        #pragma unroll
        for (int j = 0; j < 4; j++) {
            float lo, hi;
            asm("mov.b64 {%0, %1}, %2;" : "=f"(lo), "=f"(hi) : "l"(acc[i][j]));
            s += fmaxf(lo + csr[2 * j],     0.f) * w1r[2 * j]
               + fmaxf(hi + csr[2 * j + 1], 0.f) * w1r[2 * j + 1];
        }
        // reduce across the 8 h-threadcols (contiguous 8-lane groups in warp)
        s += __shfl_xor_sync(0xffffffffu, s, 1);
        s += __shfl_xor_sync(0xffffffffu, s, 2);
        s += __shfl_xor_sync(0xffffffffu, s, 4);
        const int t = thalf * T2 + t0 + i;
        if (tc == 0 && t < T_DIM) out[b * T_DIM + t] = s + bias1;
    }
}

extern "C" void kernel_launch(void* const* d_in, const int* in_sizes, int n_in,
                              void* d_out, int out_size)
{
    const float* query = (const float*)d_in[0];
    const float* keys  = (const float*)d_in[1];
    const float* W0    = (const float*)d_in[2];
    const float* b0    = (const float*)d_in[3];
    const float* W1    = (const float*)d_in[4];
    const float* b1    = (const float*)d_in[5];
    float* out = (float*)d_out;

    cudaFuncSetAttribute(lau_kernel, cudaFuncAttributeMaxDynamicSharedMemorySize, SMEM_BYTES);
    dim3 grid(B_DIM, 2);
    lau_kernel<<<grid, NTH, SMEM_BYTES>>>(query, keys, W0, b0, W1, b1, out);
}